// round 1
// baseline (speedup 1.0000x reference)
#include <cuda_runtime.h>
#include <cuda_bf16.h>
#include <math.h>

// Problem constants
#define TT 128
#define BB 256
#define DIN 512
#define H1 1024
#define H2 1024
#define H3 512

// Persistent state (ping-pong h, in-place c)
__device__ float g_h1[2][BB * H1];
__device__ float g_c1[BB * H1];
__device__ float g_h2[2][BB * H2];
__device__ float g_c2[BB * H2];
__device__ float g_h3[2][BB * H3];
__device__ float g_c3[BB * H3];

__device__ __forceinline__ float sigm(float x) {
    return 1.0f / (1.0f + __expf(-x));
}

// ---------------------------------------------------------------------------
// Fused LSTM step: gates = x @ Wih^T + h @ Whh^T + bih + bhh ; update c, h.
// Block tile: BM=64 batch rows x BN=32 hidden cols x 4 gates.
// 256 threads: jj = tid&31 (hidden col), bg = tid>>5 (8 batch rows each).
// Inner loop: x reads are warp-broadcast (same b rows across warp), weight
// reads conflict-free (padded). K loop walks K1 (input) then K2 (recurrent).
// ---------------------------------------------------------------------------
template <int H, int K1, int K2>
__global__ __launch_bounds__(256, 2)
void lstm_step_kernel(const float* __restrict__ x,     // [B, K1]
                      const float* __restrict__ hin,   // [B, K2]
                      const float* __restrict__ Wih,   // [4H, K1]
                      const float* __restrict__ Whh,   // [4H, K2]
                      const float* __restrict__ bih,   // [4H]
                      const float* __restrict__ bhh,   // [4H]
                      float* __restrict__ c,           // [B, H] in/out
                      float* __restrict__ hout)        // [B, H]
{
    constexpr int BM = 64, BN = 32, KC = 32, NT = 256;

    __shared__ float xs[BM][KC];          // [b][k] : inner reads broadcast
    __shared__ float ws[4][BN][KC + 1];   // [g][j][k] : +1 pad kills conflicts

    const int tid = threadIdx.x;
    const int jj = tid & 31;
    const int bg = tid >> 5;              // 0..7, each owns 8 batch rows
    const int j0 = blockIdx.x * BN;
    const int b0 = blockIdx.y * BM;

    float acc[4][8];
#pragma unroll
    for (int g = 0; g < 4; ++g)
#pragma unroll
        for (int i = 0; i < 8; ++i) acc[g][i] = 0.0f;

    for (int k0 = 0; k0 < K1 + K2; k0 += KC) {
        const float* src;
        const float* W;
        int ks, ld;
        if (k0 < K1) { src = x;   W = Wih; ks = k0;      ld = K1; }
        else         { src = hin; W = Whh; ks = k0 - K1; ld = K2; }

        __syncthreads();
        // load x/h tile: 64x32 = 2048 elems, 8 per thread, coalesced
#pragma unroll
        for (int it = 0; it < (BM * KC) / NT; ++it) {
            int idx = tid + it * NT;
            int b = idx >> 5, kk = idx & 31;
            xs[b][kk] = src[(size_t)(b0 + b) * ld + ks + kk];
        }
        // load weight tiles for 4 gates: 4x32x32 = 4096 elems, coalesced rows
#pragma unroll
        for (int it = 0; it < (4 * BN * KC) / NT; ++it) {
            int idx = tid + it * NT;
            int kk = idx & 31, jw = (idx >> 5) & 31, g = idx >> 10;
            ws[g][jw][kk] = W[(size_t)(g * H + j0 + jw) * ld + ks + kk];
        }
        __syncthreads();

#pragma unroll
        for (int kk = 0; kk < KC; ++kk) {
            float xv[8];
#pragma unroll
            for (int i = 0; i < 8; ++i) xv[i] = xs[bg * 8 + i][kk];
#pragma unroll
            for (int g = 0; g < 4; ++g) {
                float wv = ws[g][jj][kk];
#pragma unroll
                for (int i = 0; i < 8; ++i)
                    acc[g][i] = fmaf(xv[i], wv, acc[g][i]);
            }
        }
    }

    // Epilogue: bias + activations + state update
    const int j = j0 + jj;
    const float bi = bih[0 * H + j] + bhh[0 * H + j];
    const float bf = bih[1 * H + j] + bhh[1 * H + j];
    const float bg_ = bih[2 * H + j] + bhh[2 * H + j];
    const float bo = bih[3 * H + j] + bhh[3 * H + j];

#pragma unroll
    for (int i = 0; i < 8; ++i) {
        const int b = b0 + bg * 8 + i;
        const size_t off = (size_t)b * H + j;
        float ig = sigm(acc[0][i] + bi);
        float fg = sigm(acc[1][i] + bf);
        float gg = tanhf(acc[2][i] + bg_);
        float og = sigm(acc[3][i] + bo);
        float cn = fg * c[off] + ig * gg;
        c[off] = cn;
        hout[off] = og * tanhf(cn);
    }
}

// Zero all state buffers
__global__ void init_state_kernel() {
    int idx = blockIdx.x * blockDim.x + threadIdx.x;
    int stride = gridDim.x * blockDim.x;
    const int N1 = BB * H1, N3 = BB * H3;
    for (int i = idx; i < N1; i += stride) {
        g_h1[0][i] = 0.f; g_h1[1][i] = 0.f; g_c1[i] = 0.f;
        g_h2[0][i] = 0.f; g_h2[1][i] = 0.f; g_c2[i] = 0.f;
    }
    for (int i = idx; i < N3; i += stride) {
        g_h3[0][i] = 0.f; g_h3[1][i] = 0.f; g_c3[i] = 0.f;
    }
}

// Write final (h1, c1, h2, c2, h3, c3) to d_out. Final h buffers: index 0
// (after 128 steps the write buffer has wrapped back to 0).
__global__ void finalize_kernel(float* __restrict__ out) {
    int idx = blockIdx.x * blockDim.x + threadIdx.x;
    int stride = gridDim.x * blockDim.x;
    const int N1 = BB * H1, N3 = BB * H3;
    for (int i = idx; i < N1; i += stride) {
        out[0 * N1 + i] = g_h1[0][i];
        out[1 * N1 + i] = g_c1[i];
        out[2 * N1 + i] = g_h2[0][i];
        out[3 * N1 + i] = g_c2[i];
    }
    for (int i = idx; i < N3; i += stride) {
        out[4 * N1 + i] = g_h3[0][i];
        out[4 * N1 + N3 + i] = g_c3[i];
    }
}

extern "C" void kernel_launch(void* const* d_in, const int* in_sizes, int n_in,
                              void* d_out, int out_size) {
    const float* x    = (const float*)d_in[0];
    const float* Wih1 = (const float*)d_in[1];
    const float* Whh1 = (const float*)d_in[2];
    const float* bih1 = (const float*)d_in[3];
    const float* bhh1 = (const float*)d_in[4];
    const float* Wih2 = (const float*)d_in[5];
    const float* Whh2 = (const float*)d_in[6];
    const float* bih2 = (const float*)d_in[7];
    const float* bhh2 = (const float*)d_in[8];
    const float* Wih3 = (const float*)d_in[9];
    const float* Whh3 = (const float*)d_in[10];
    const float* bih3 = (const float*)d_in[11];
    const float* bhh3 = (const float*)d_in[12];
    float* out = (float*)d_out;

    float *h1, *c1, *h2, *c2, *h3, *c3;
    cudaGetSymbolAddress((void**)&h1, g_h1);
    cudaGetSymbolAddress((void**)&c1, g_c1);
    cudaGetSymbolAddress((void**)&h2, g_h2);
    cudaGetSymbolAddress((void**)&c2, g_c2);
    cudaGetSymbolAddress((void**)&h3, g_h3);
    cudaGetSymbolAddress((void**)&c3, g_c3);

    init_state_kernel<<<256, 256>>>();

    const int N1 = BB * H1, N3 = BB * H3;

    for (int t = 0; t < TT; ++t) {
        const int pi = t & 1, po = (t + 1) & 1;
        const float* x_t = x + (size_t)t * BB * DIN;

        lstm_step_kernel<H1, DIN, H1><<<dim3(H1 / 32, BB / 64), 256>>>(
            x_t, h1 + pi * N1, Wih1, Whh1, bih1, bhh1, c1, h1 + po * N1);

        lstm_step_kernel<H2, H1, H2><<<dim3(H2 / 32, BB / 64), 256>>>(
            h1 + po * N1, h2 + pi * N1, Wih2, Whh2, bih2, bhh2, c2, h2 + po * N1);

        lstm_step_kernel<H3, H2, H3><<<dim3(H3 / 32, BB / 64), 256>>>(
            h2 + po * N1, h3 + pi * N3, Wih3, Whh3, bih3, bhh3, c3, h3 + po * N3);
    }

    finalize_kernel<<<256, 256>>>(out);
}

// round 2
// speedup vs baseline: 1.6948x; 1.6948x over previous
#include <cuda_runtime.h>
#include <cuda_bf16.h>
#include <math.h>

#define TT 128
#define BB 256
#define DIN 512
#define H1 1024
#define H2 1024
#define H3 512

typedef __nv_bfloat16 bf16;

// ---------------- persistent device storage (no allocs allowed) -------------
__device__ bf16 g_x_hi[TT * BB * DIN];
__device__ bf16 g_x_lo[TT * BB * DIN];

__device__ bf16 g_W1i_hi[4 * H1 * DIN], g_W1i_lo[4 * H1 * DIN];
__device__ bf16 g_W1h_hi[4 * H1 * H1],  g_W1h_lo[4 * H1 * H1];
__device__ bf16 g_W2i_hi[4 * H2 * H1],  g_W2i_lo[4 * H2 * H1];
__device__ bf16 g_W2h_hi[4 * H2 * H2],  g_W2h_lo[4 * H2 * H2];
__device__ bf16 g_W3i_hi[4 * H3 * H2],  g_W3i_lo[4 * H3 * H2];
__device__ bf16 g_W3h_hi[4 * H3 * H3],  g_W3h_lo[4 * H3 * H3];

__device__ bf16 g_h1_hi[2][BB * H1], g_h1_lo[2][BB * H1];
__device__ bf16 g_h2_hi[2][BB * H2], g_h2_lo[2][BB * H2];
__device__ bf16 g_h3_hi[2][BB * H3], g_h3_lo[2][BB * H3];

__device__ float g_c1[BB * H1], g_c2[BB * H2], g_c3[BB * H3];
__device__ float g_hf1[BB * H1], g_hf2[BB * H2], g_hf3[BB * H3];

// ---------------- small helpers ---------------------------------------------
__device__ __forceinline__ void cp16(void* smem, const void* gmem) {
    unsigned s = (unsigned)__cvta_generic_to_shared(smem);
    asm volatile("cp.async.cg.shared.global [%0], [%1], 16;\n" ::"r"(s), "l"(gmem));
}
#define CP_COMMIT() asm volatile("cp.async.commit_group;\n" ::: "memory")
#define CP_WAIT1()  asm volatile("cp.async.wait_group 1;\n" ::: "memory")
#define CP_WAIT0()  asm volatile("cp.async.wait_group 0;\n" ::: "memory")

__device__ __forceinline__ void mma_bf16(float* c, const unsigned* a, const unsigned* b) {
    asm volatile(
        "mma.sync.aligned.m16n8k16.row.col.f32.bf16.bf16.f32 "
        "{%0,%1,%2,%3},{%4,%5,%6,%7},{%8,%9},{%0,%1,%2,%3};\n"
        : "+f"(c[0]), "+f"(c[1]), "+f"(c[2]), "+f"(c[3])
        : "r"(a[0]), "r"(a[1]), "r"(a[2]), "r"(a[3]), "r"(b[0]), "r"(b[1]));
}

__device__ __forceinline__ float sigm(float x) { return 1.0f / (1.0f + __expf(-x)); }

// ---------------------------------------------------------------------------
// Fused LSTM step on tensor cores (bf16 3-term split = fp32-grade accuracy).
// C[b, g*H+j] = A' @ B'^T over Keff = 3*(K1+K2):
//   term 0: x_hi (.) W_hi   term 1: x_lo (.) W_hi   term 2: x_hi (.) W_lo
// Block: 64 batch x (16 j x 4 gates). 8 warps = 2(m) x 4(gate).
// ---------------------------------------------------------------------------
template <int H, int K1, int K2>
__global__ __launch_bounds__(256, 2)
void lstm_mma_kernel(const bf16* __restrict__ Ai_hi, const bf16* __restrict__ Ai_lo,  // [BB,K1]
                     const bf16* __restrict__ Ah_hi, const bf16* __restrict__ Ah_lo,  // [BB,K2]
                     const bf16* __restrict__ Wi_hi, const bf16* __restrict__ Wi_lo,  // [4H,K1]
                     const bf16* __restrict__ Wh_hi, const bf16* __restrict__ Wh_lo,  // [4H,K2]
                     const float* __restrict__ bih, const float* __restrict__ bhh,
                     float* __restrict__ c, float* __restrict__ hf,
                     bf16* __restrict__ ho_hi, bf16* __restrict__ ho_lo)
{
    constexpr int KK = K1 + K2;
    constexpr int NCH = 3 * KK / 32;   // k-chunks of 32 bf16

    __shared__ __align__(16) bf16 As[2][64][40];   // [stage][batch][k] pitch 40
    __shared__ __align__(16) bf16 Bs[2][64][40];   // [stage][gate*16+j][k]
    __shared__ float gsm[4][64][17];               // [gate][batch][j]

    const int tid = threadIdx.x;
    const int j0 = blockIdx.x * 16;
    const int b0 = blockIdx.y * 64;

    const int lr = tid >> 2, lq = tid & 3;          // loader: row, 16B quad
    const int wid = tid >> 5, lane = tid & 31;
    const int wm = wid >> 2, wn = wid & 3;          // warp m-half, gate
    const int g = lane >> 2, tg = lane & 3;

    float acc[2][2][4];
#pragma unroll
    for (int mi = 0; mi < 2; ++mi)
#pragma unroll
        for (int nj = 0; nj < 2; ++nj)
#pragma unroll
            for (int r = 0; r < 4; ++r) acc[mi][nj][r] = 0.0f;

    auto load_tiles = [&](int kb, int s) {
        const int kglob = kb * 32;
        const int term = kglob / KK;
        const int kk = kglob - term * KK;
        // A operand
        {
            const bf16* src; int ld, col;
            const bool lo_a = (term == 1);
            if (kk < K1) { src = lo_a ? Ai_lo : Ai_hi; ld = K1; col = kk; }
            else         { src = lo_a ? Ah_lo : Ah_hi; ld = K2; col = kk - K1; }
            cp16(&As[s][lr][lq * 8], src + (size_t)(b0 + lr) * ld + col + lq * 8);
        }
        // B operand (weights, row-major [4H][K] == col-major K x N)
        {
            const bf16* src; int ld, col;
            const bool lo_b = (term == 2);
            if (kk < K1) { src = lo_b ? Wi_lo : Wi_hi; ld = K1; col = kk; }
            else         { src = lo_b ? Wh_lo : Wh_hi; ld = K2; col = kk - K1; }
            const int gate = lr >> 4, jl = lr & 15;
            cp16(&Bs[s][lr][lq * 8], src + (size_t)(gate * H + j0 + jl) * ld + col + lq * 8);
        }
    };

    auto compute = [&](int s) {
#pragma unroll
        for (int kh = 0; kh < 2; ++kh) {
            unsigned a[2][4], b[2][2];
#pragma unroll
            for (int mi = 0; mi < 2; ++mi) {
                const int r = wm * 32 + mi * 16 + g;
                const int kc = kh * 16 + tg * 2;
                a[mi][0] = *(const unsigned*)&As[s][r][kc];
                a[mi][1] = *(const unsigned*)&As[s][r + 8][kc];
                a[mi][2] = *(const unsigned*)&As[s][r][kc + 8];
                a[mi][3] = *(const unsigned*)&As[s][r + 8][kc + 8];
            }
#pragma unroll
            for (int nj = 0; nj < 2; ++nj) {
                const int r = wn * 16 + nj * 8 + g;
                const int kc = kh * 16 + tg * 2;
                b[nj][0] = *(const unsigned*)&Bs[s][r][kc];
                b[nj][1] = *(const unsigned*)&Bs[s][r][kc + 8];
            }
#pragma unroll
            for (int mi = 0; mi < 2; ++mi)
#pragma unroll
                for (int nj = 0; nj < 2; ++nj)
                    mma_bf16(acc[mi][nj], a[mi], b[nj]);
        }
    };

    load_tiles(0, 0);
    CP_COMMIT();
    for (int kb = 0; kb < NCH; ++kb) {
        const int s = kb & 1;
        if (kb + 1 < NCH) {
            load_tiles(kb + 1, (kb + 1) & 1);
            CP_COMMIT();
            CP_WAIT1();
        } else {
            CP_WAIT0();
        }
        __syncthreads();
        compute(s);
        __syncthreads();
    }

    // stage gates to smem so each thread can combine i,f,g,o for one (b,j)
#pragma unroll
    for (int mi = 0; mi < 2; ++mi)
#pragma unroll
        for (int nj = 0; nj < 2; ++nj) {
            const int r0 = wm * 32 + mi * 16 + g;
            const int jc = nj * 8 + tg * 2;
            gsm[wn][r0][jc]     = acc[mi][nj][0];
            gsm[wn][r0][jc + 1] = acc[mi][nj][1];
            gsm[wn][r0 + 8][jc]     = acc[mi][nj][2];
            gsm[wn][r0 + 8][jc + 1] = acc[mi][nj][3];
        }
    __syncthreads();

#pragma unroll
    for (int it = 0; it < 4; ++it) {
        const int e = tid + it * 256;
        const int bl = e >> 4, jl = e & 15;
        const int j = j0 + jl;
        const int b = b0 + bl;
        const size_t off = (size_t)b * H + j;
        const float gi = gsm[0][bl][jl] + bih[0 * H + j] + bhh[0 * H + j];
        const float gf = gsm[1][bl][jl] + bih[1 * H + j] + bhh[1 * H + j];
        const float gg = gsm[2][bl][jl] + bih[2 * H + j] + bhh[2 * H + j];
        const float go = gsm[3][bl][jl] + bih[3 * H + j] + bhh[3 * H + j];
        const float i_ = sigm(gi);
        const float f_ = sigm(gf);
        const float g_ = tanhf(gg);
        const float o_ = sigm(go);
        const float cn = f_ * c[off] + i_ * g_;
        c[off] = cn;
        const float hn = o_ * tanhf(cn);
        hf[off] = hn;
        const bf16 hh = __float2bfloat16(hn);
        ho_hi[off] = hh;
        ho_lo[off] = __float2bfloat16(hn - __bfloat162float(hh));
    }
}

// ---------------- prep / init / finalize ------------------------------------
__global__ void split_kernel(const float* __restrict__ src, bf16* __restrict__ hi,
                             bf16* __restrict__ lo, int n) {
    int i = blockIdx.x * blockDim.x + threadIdx.x;
    const int st = gridDim.x * blockDim.x;
    for (; i < n; i += st) {
        const float v = src[i];
        const bf16 h = __float2bfloat16(v);
        hi[i] = h;
        lo[i] = __float2bfloat16(v - __bfloat162float(h));
    }
}

__global__ void init_state_kernel() {
    int idx = blockIdx.x * blockDim.x + threadIdx.x;
    const int st = gridDim.x * blockDim.x;
    const int N1 = BB * H1, N3 = BB * H3;
    const bf16 z = __float2bfloat16(0.0f);
    for (int i = idx; i < N1; i += st) {
        g_h1_hi[0][i] = z; g_h1_lo[0][i] = z; g_h1_hi[1][i] = z; g_h1_lo[1][i] = z;
        g_h2_hi[0][i] = z; g_h2_lo[0][i] = z; g_h2_hi[1][i] = z; g_h2_lo[1][i] = z;
        g_c1[i] = 0.f; g_c2[i] = 0.f;
    }
    for (int i = idx; i < N3; i += st) {
        g_h3_hi[0][i] = z; g_h3_lo[0][i] = z; g_h3_hi[1][i] = z; g_h3_lo[1][i] = z;
        g_c3[i] = 0.f;
    }
}

__global__ void finalize_kernel(float* __restrict__ out) {
    int idx = blockIdx.x * blockDim.x + threadIdx.x;
    const int st = gridDim.x * blockDim.x;
    const int N1 = BB * H1, N3 = BB * H3;
    for (int i = idx; i < N1; i += st) {
        out[0 * N1 + i] = g_hf1[i];
        out[1 * N1 + i] = g_c1[i];
        out[2 * N1 + i] = g_hf2[i];
        out[3 * N1 + i] = g_c2[i];
    }
    for (int i = idx; i < N3; i += st) {
        out[4 * N1 + i] = g_hf3[i];
        out[4 * N1 + N3 + i] = g_c3[i];
    }
}

// ---------------- launch ----------------------------------------------------
extern "C" void kernel_launch(void* const* d_in, const int* in_sizes, int n_in,
                              void* d_out, int out_size) {
    const float* x    = (const float*)d_in[0];
    const float* Wih1 = (const float*)d_in[1];
    const float* Whh1 = (const float*)d_in[2];
    const float* bih1 = (const float*)d_in[3];
    const float* bhh1 = (const float*)d_in[4];
    const float* Wih2 = (const float*)d_in[5];
    const float* Whh2 = (const float*)d_in[6];
    const float* bih2 = (const float*)d_in[7];
    const float* bhh2 = (const float*)d_in[8];
    const float* Wih3 = (const float*)d_in[9];
    const float* Whh3 = (const float*)d_in[10];
    const float* bih3 = (const float*)d_in[11];
    const float* bhh3 = (const float*)d_in[12];
    float* out = (float*)d_out;

    bf16 *x_hi, *x_lo;
    bf16 *W1i_hi, *W1i_lo, *W1h_hi, *W1h_lo;
    bf16 *W2i_hi, *W2i_lo, *W2h_hi, *W2h_lo;
    bf16 *W3i_hi, *W3i_lo, *W3h_hi, *W3h_lo;
    bf16 *h1_hi, *h1_lo, *h2_hi, *h2_lo, *h3_hi, *h3_lo;
    float *c1, *c2, *c3, *hf1, *hf2, *hf3;

    cudaGetSymbolAddress((void**)&x_hi, g_x_hi);
    cudaGetSymbolAddress((void**)&x_lo, g_x_lo);
    cudaGetSymbolAddress((void**)&W1i_hi, g_W1i_hi);
    cudaGetSymbolAddress((void**)&W1i_lo, g_W1i_lo);
    cudaGetSymbolAddress((void**)&W1h_hi, g_W1h_hi);
    cudaGetSymbolAddress((void**)&W1h_lo, g_W1h_lo);
    cudaGetSymbolAddress((void**)&W2i_hi, g_W2i_hi);
    cudaGetSymbolAddress((void**)&W2i_lo, g_W2i_lo);
    cudaGetSymbolAddress((void**)&W2h_hi, g_W2h_hi);
    cudaGetSymbolAddress((void**)&W2h_lo, g_W2h_lo);
    cudaGetSymbolAddress((void**)&W3i_hi, g_W3i_hi);
    cudaGetSymbolAddress((void**)&W3i_lo, g_W3i_lo);
    cudaGetSymbolAddress((void**)&W3h_hi, g_W3h_hi);
    cudaGetSymbolAddress((void**)&W3h_lo, g_W3h_lo);
    cudaGetSymbolAddress((void**)&h1_hi, g_h1_hi);
    cudaGetSymbolAddress((void**)&h1_lo, g_h1_lo);
    cudaGetSymbolAddress((void**)&h2_hi, g_h2_hi);
    cudaGetSymbolAddress((void**)&h2_lo, g_h2_lo);
    cudaGetSymbolAddress((void**)&h3_hi, g_h3_hi);
    cudaGetSymbolAddress((void**)&h3_lo, g_h3_lo);
    cudaGetSymbolAddress((void**)&c1, g_c1);
    cudaGetSymbolAddress((void**)&c2, g_c2);
    cudaGetSymbolAddress((void**)&c3, g_c3);
    cudaGetSymbolAddress((void**)&hf1, g_hf1);
    cudaGetSymbolAddress((void**)&hf2, g_hf2);
    cudaGetSymbolAddress((void**)&hf3, g_hf3);

    // prep: split inputs + weights to (hi, lo) bf16, zero state
    split_kernel<<<2048, 256>>>(x, x_hi, x_lo, TT * BB * DIN);
    split_kernel<<<1024, 256>>>(Wih1, W1i_hi, W1i_lo, 4 * H1 * DIN);
    split_kernel<<<1024, 256>>>(Whh1, W1h_hi, W1h_lo, 4 * H1 * H1);
    split_kernel<<<1024, 256>>>(Wih2, W2i_hi, W2i_lo, 4 * H2 * H1);
    split_kernel<<<1024, 256>>>(Whh2, W2h_hi, W2h_lo, 4 * H2 * H2);
    split_kernel<<<1024, 256>>>(Wih3, W3i_hi, W3i_lo, 4 * H3 * H2);
    split_kernel<<<1024, 256>>>(Whh3, W3h_hi, W3h_lo, 4 * H3 * H3);
    init_state_kernel<<<512, 256>>>();

    const int N1 = BB * H1, N2 = BB * H2, N3 = BB * H3;

    for (int t = 0; t < TT; ++t) {
        const int pi = t & 1, po = (t + 1) & 1;
        const bf16* xt_hi = x_hi + (size_t)t * BB * DIN;
        const bf16* xt_lo = x_lo + (size_t)t * BB * DIN;

        lstm_mma_kernel<H1, DIN, H1><<<dim3(H1 / 16, 4), 256>>>(
            xt_hi, xt_lo, h1_hi + pi * N1, h1_lo + pi * N1,
            W1i_hi, W1i_lo, W1h_hi, W1h_lo, bih1, bhh1,
            c1, hf1, h1_hi + po * N1, h1_lo + po * N1);

        lstm_mma_kernel<H2, H1, H2><<<dim3(H2 / 16, 4), 256>>>(
            h1_hi + po * N1, h1_lo + po * N1, h2_hi + pi * N2, h2_lo + pi * N2,
            W2i_hi, W2i_lo, W2h_hi, W2h_lo, bih2, bhh2,
            c2, hf2, h2_hi + po * N2, h2_lo + po * N2);

        lstm_mma_kernel<H3, H2, H3><<<dim3(H3 / 16, 4), 256>>>(
            h2_hi + po * N2, h2_lo + po * N2, h3_hi + pi * N3, h3_lo + pi * N3,
            W3i_hi, W3i_lo, W3h_hi, W3h_lo, bih3, bhh3,
            c3, hf3, h3_hi + po * N3, h3_lo + po * N3);
    }

    finalize_kernel<<<256, 256>>>(out);
}

// round 4
// speedup vs baseline: 2.6245x; 1.5486x over previous
#include <cuda_runtime.h>
#include <cuda_bf16.h>
#include <math.h>
#include <cstdint>

#define TT 128
#define BB 256
#define DIN 512
#define H1 1024
#define H2 1024
#define H3 512

typedef __nv_bfloat16 bf16;

// ---------------- persistent device storage ---------------------------------
__device__ bf16 g_x_hi[TT * BB * DIN];
__device__ bf16 g_x_lo[TT * BB * DIN];

__device__ bf16 g_W1i_hi[4 * H1 * DIN], g_W1i_lo[4 * H1 * DIN];
__device__ bf16 g_W1h_hi[4 * H1 * H1],  g_W1h_lo[4 * H1 * H1];
__device__ bf16 g_W2i_hi[4 * H2 * H1],  g_W2i_lo[4 * H2 * H1];
__device__ bf16 g_W2h_hi[4 * H2 * H2],  g_W2h_lo[4 * H2 * H2];
__device__ bf16 g_W3i_hi[4 * H3 * H2],  g_W3i_lo[4 * H3 * H2];
__device__ bf16 g_W3h_hi[4 * H3 * H3],  g_W3h_lo[4 * H3 * H3];

__device__ bf16 g_h1_hi[BB * H1], g_h1_lo[BB * H1];
__device__ bf16 g_h2_hi[BB * H2], g_h2_lo[BB * H2];
__device__ bf16 g_h3_hi[BB * H3], g_h3_lo[BB * H3];

__device__ float g_c1[BB * H1], g_c2[BB * H2], g_c3[BB * H3];
__device__ float g_hf1[BB * H1], g_hf2[BB * H2], g_hf3[BB * H3];

// ---------------- helpers ----------------------------------------------------
__device__ __forceinline__ uint32_t smem_u32(const void* p) {
    uint32_t a;
    asm("{ .reg .u64 t; cvta.to.shared.u64 t, %1; cvt.u32.u64 %0, t; }" : "=r"(a) : "l"(p));
    return a;
}
__device__ __forceinline__ void cp16(uint32_t smem, const void* gmem) {
    asm volatile("cp.async.cg.shared.global [%0], [%1], 16;\n" ::"r"(smem), "l"(gmem));
}
#define CP_COMMIT() asm volatile("cp.async.commit_group;\n" ::: "memory")
#define CP_WAIT(n)  asm volatile("cp.async.wait_group %0;\n" ::"n"(n) : "memory")

__device__ __forceinline__ void ldsm4(unsigned* d, uint32_t addr) {
    asm volatile("ldmatrix.sync.aligned.m8n8.x4.shared.b16 {%0,%1,%2,%3}, [%4];"
                 : "=r"(d[0]), "=r"(d[1]), "=r"(d[2]), "=r"(d[3]) : "r"(addr));
}
__device__ __forceinline__ void mma_bf16(float* c, const unsigned* a, unsigned b0, unsigned b1) {
    asm volatile(
        "mma.sync.aligned.m16n8k16.row.col.f32.bf16.bf16.f32 "
        "{%0,%1,%2,%3},{%4,%5,%6,%7},{%8,%9},{%0,%1,%2,%3};\n"
        : "+f"(c[0]), "+f"(c[1]), "+f"(c[2]), "+f"(c[3])
        : "r"(a[0]), "r"(a[1]), "r"(a[2]), "r"(a[3]), "r"(b0), "r"(b1));
}
__device__ __forceinline__ float sigm(float x) { return 1.0f / (1.0f + __expf(-x)); }

// ---------------------------------------------------------------------------
// Fused LSTM step on mma.sync tensor cores, bf16 3-term split.
// Block: 64 batch x (16 j x 4 gates). 8 warps = 2(m) x 4(gate).
// KC=64 chunks, 4-stage cp.async pipeline, 1 syncthreads per chunk,
// ldmatrix fragment loads. Smem pitch 72 (bank-conflict-free perm).
// ---------------------------------------------------------------------------
#define PITCH 72
#define STG_HALF (64 * PITCH)            // bf16 elems per A (or B) stage
#define STG_ELEMS (2 * STG_HALF)         // per full stage
#define DYN_SMEM_BYTES (4 * STG_ELEMS * 2)

template <int K1, int K2>
__global__ __launch_bounds__(256, 2)
void lstm_mma_kernel(const bf16* __restrict__ Ai_hi, const bf16* __restrict__ Ai_lo,  // [BB,K1]
                     const bf16* __restrict__ Ah_hi, const bf16* __restrict__ Ah_lo,  // [BB,K2]
                     const bf16* __restrict__ Wi_hi, const bf16* __restrict__ Wi_lo,  // [4H,K1]
                     const bf16* __restrict__ Wh_hi, const bf16* __restrict__ Wh_lo,  // [4H,K2]
                     const float* __restrict__ bih, const float* __restrict__ bhh,
                     float* __restrict__ c, float* __restrict__ hf,
                     bf16* __restrict__ ho_hi, bf16* __restrict__ ho_lo)
{
    constexpr int KK = K1 + K2;
    constexpr int NCH = 3 * KK / 64;
    constexpr int H = KK - K1;  // H == K2

    extern __shared__ __align__(16) bf16 dyn[];
    __shared__ float gsm[4][64][17];

    const uint32_t sbase = smem_u32(dyn);
    const int tid = threadIdx.x;
    const int wid = tid >> 5, lane = tid & 31;
    const int wm = wid >> 2, wn = wid & 3;
    const int j0 = blockIdx.x * 16;
    const int b0 = blockIdx.y * 64;

    float acc[2][2][4];
#pragma unroll
    for (int mi = 0; mi < 2; ++mi)
#pragma unroll
        for (int nj = 0; nj < 2; ++nj)
#pragma unroll
            for (int r = 0; r < 4; ++r) acc[mi][nj][r] = 0.0f;

    // loader indices: each thread does 2 cp16 for A + 2 for B
    const int lr = tid >> 3, lq = tid & 7;   // rows 0..31 (x2), quad 0..7

    auto load_stage = [&](int ci, int s) {
        const int kg = ci * 64;
        const int term = kg / KK;
        const int kk = kg - term * KK;
        const bf16 *A, *W;
        int col, ld;
        if (kk < K1) {
            A = (term == 1) ? Ai_lo : Ai_hi;
            W = (term == 2) ? Wi_lo : Wi_hi;
            col = kk; ld = K1;
        } else {
            A = (term == 1) ? Ah_lo : Ah_hi;
            W = (term == 2) ? Wh_lo : Wh_hi;
            col = kk - K1; ld = K2;
        }
        const uint32_t abase = sbase + (uint32_t)(s * STG_ELEMS) * 2;
        const uint32_t bbase = abase + STG_HALF * 2;
#pragma unroll
        for (int it = 0; it < 2; ++it) {
            const int r = lr + it * 32;
            cp16(abase + (uint32_t)(r * PITCH + lq * 8) * 2,
                 A + (size_t)(b0 + r) * ld + col + lq * 8);
        }
        const int gate = lr >> 4, jl = lr & 15;       // B row = gate*16+jl
#pragma unroll
        for (int it = 0; it < 2; ++it) {
            const int r = lr + it * 32;
            const int gate2 = r >> 4, jl2 = r & 15;
            cp16(bbase + (uint32_t)(r * PITCH + lq * 8) * 2,
                 W + (size_t)(gate2 * H + j0 + jl2) * ld + col + lq * 8);
        }
        (void)gate; (void)jl;
        CP_COMMIT();
    };

    auto compute = [&](int s) {
        const uint32_t abase = sbase + (uint32_t)(s * STG_ELEMS) * 2;
        const uint32_t bbase = abase + STG_HALF * 2;
        // ldmatrix source rows/cols for this lane
        const int arow_off = lane & 15, acol_off = (lane >> 4) << 3;
        const int brow_off = (((lane >> 3) & 1) << 3) + (lane & 7);
        const int bcol_off = (lane >> 4) << 3;
#pragma unroll
        for (int kh = 0; kh < 4; ++kh) {
            const int kc = kh * 16;
            unsigned a[2][4], b[4];
#pragma unroll
            for (int mi = 0; mi < 2; ++mi) {
                const int row = wm * 32 + mi * 16 + arow_off;
                ldsm4(a[mi], abase + (uint32_t)(row * PITCH + kc + acol_off) * 2);
            }
            {
                const int row = wn * 16 + brow_off;
                ldsm4(b, bbase + (uint32_t)(row * PITCH + kc + bcol_off) * 2);
            }
#pragma unroll
            for (int mi = 0; mi < 2; ++mi)
#pragma unroll
                for (int nj = 0; nj < 2; ++nj)
                    mma_bf16(acc[mi][nj], a[mi], b[nj], b[nj + 2]);
        }
    };

    load_stage(0, 0);
    load_stage(1, 1);
    load_stage(2, 2);

    for (int ci = 0; ci < NCH; ++ci) {
        const int rem = NCH - 1 - ci;
        if (rem >= 2)      { CP_WAIT(2); }
        else if (rem == 1) { CP_WAIT(1); }
        else               { CP_WAIT(0); }
        __syncthreads();
        if (ci + 3 < NCH) load_stage(ci + 3, (ci + 3) & 3);
        compute(ci & 3);
    }

    // stage gates to smem; combine i,f,g,o per (b,j)
    const int g = lane >> 2, tg = lane & 3;
#pragma unroll
    for (int mi = 0; mi < 2; ++mi)
#pragma unroll
        for (int nj = 0; nj < 2; ++nj) {
            const int r0 = wm * 32 + mi * 16 + g;
            const int jc = nj * 8 + tg * 2;
            gsm[wn][r0][jc]         = acc[mi][nj][0];
            gsm[wn][r0][jc + 1]     = acc[mi][nj][1];
            gsm[wn][r0 + 8][jc]     = acc[mi][nj][2];
            gsm[wn][r0 + 8][jc + 1] = acc[mi][nj][3];
        }
    __syncthreads();

#pragma unroll
    for (int it = 0; it < 4; ++it) {
        const int e = tid + it * 256;
        const int bl = e >> 4, jl = e & 15;
        const int j = j0 + jl;
        const int b = b0 + bl;
        const size_t off = (size_t)b * H + j;
        const float gi = gsm[0][bl][jl] + bih[0 * H + j] + bhh[0 * H + j];
        const float gf = gsm[1][bl][jl] + bih[1 * H + j] + bhh[1 * H + j];
        const float gg = gsm[2][bl][jl] + bih[2 * H + j] + bhh[2 * H + j];
        const float go = gsm[3][bl][jl] + bih[3 * H + j] + bhh[3 * H + j];
        const float i_ = sigm(gi);
        const float f_ = sigm(gf);
        const float g_ = tanhf(gg);
        const float o_ = sigm(go);
        const float cn = f_ * c[off] + i_ * g_;
        c[off] = cn;
        const float hn = o_ * tanhf(cn);
        hf[off] = hn;
        const bf16 hh = __float2bfloat16(hn);
        ho_hi[off] = hh;
        ho_lo[off] = __float2bfloat16(hn - __bfloat162float(hh));
    }
}

// ---------------- prep / init / finalize ------------------------------------
__global__ void split_kernel(const float* __restrict__ src, bf16* __restrict__ hi,
                             bf16* __restrict__ lo, int n) {
    int i = blockIdx.x * blockDim.x + threadIdx.x;
    const int st = gridDim.x * blockDim.x;
    for (; i < n; i += st) {
        const float v = src[i];
        const bf16 h = __float2bfloat16(v);
        hi[i] = h;
        lo[i] = __float2bfloat16(v - __bfloat162float(h));
    }
}

__global__ void init_state_kernel() {
    int idx = blockIdx.x * blockDim.x + threadIdx.x;
    const int st = gridDim.x * blockDim.x;
    const int N1 = BB * H1, N3 = BB * H3;
    const bf16 z = __float2bfloat16(0.0f);
    for (int i = idx; i < N1; i += st) {
        g_h1_hi[i] = z; g_h1_lo[i] = z;
        g_h2_hi[i] = z; g_h2_lo[i] = z;
        g_c1[i] = 0.f; g_c2[i] = 0.f;
    }
    for (int i = idx; i < N3; i += st) {
        g_h3_hi[i] = z; g_h3_lo[i] = z;
        g_c3[i] = 0.f;
    }
}

__global__ void finalize_kernel(float* __restrict__ out) {
    int idx = blockIdx.x * blockDim.x + threadIdx.x;
    const int st = gridDim.x * blockDim.x;
    const int N1 = BB * H1, N3 = BB * H3;
    for (int i = idx; i < N1; i += st) {
        out[0 * N1 + i] = g_hf1[i];
        out[1 * N1 + i] = g_c1[i];
        out[2 * N1 + i] = g_hf2[i];
        out[3 * N1 + i] = g_c2[i];
    }
    for (int i = idx; i < N3; i += st) {
        out[4 * N1 + i] = g_hf3[i];
        out[4 * N1 + N3 + i] = g_c3[i];
    }
}

// ---------------- launch ----------------------------------------------------
extern "C" void kernel_launch(void* const* d_in, const int* in_sizes, int n_in,
                              void* d_out, int out_size) {
    const float* x    = (const float*)d_in[0];
    const float* Wih1 = (const float*)d_in[1];
    const float* Whh1 = (const float*)d_in[2];
    const float* bih1 = (const float*)d_in[3];
    const float* bhh1 = (const float*)d_in[4];
    const float* Wih2 = (const float*)d_in[5];
    const float* Whh2 = (const float*)d_in[6];
    const float* bih2 = (const float*)d_in[7];
    const float* bhh2 = (const float*)d_in[8];
    const float* Wih3 = (const float*)d_in[9];
    const float* Whh3 = (const float*)d_in[10];
    const float* bih3 = (const float*)d_in[11];
    const float* bhh3 = (const float*)d_in[12];
    float* out = (float*)d_out;

    bf16 *x_hi, *x_lo;
    bf16 *W1i_hi, *W1i_lo, *W1h_hi, *W1h_lo;
    bf16 *W2i_hi, *W2i_lo, *W2h_hi, *W2h_lo;
    bf16 *W3i_hi, *W3i_lo, *W3h_hi, *W3h_lo;
    bf16 *h1_hi, *h1_lo, *h2_hi, *h2_lo, *h3_hi, *h3_lo;
    float *c1, *c2, *c3, *hf1, *hf2, *hf3;

    cudaGetSymbolAddress((void**)&x_hi, g_x_hi);
    cudaGetSymbolAddress((void**)&x_lo, g_x_lo);
    cudaGetSymbolAddress((void**)&W1i_hi, g_W1i_hi);
    cudaGetSymbolAddress((void**)&W1i_lo, g_W1i_lo);
    cudaGetSymbolAddress((void**)&W1h_hi, g_W1h_hi);
    cudaGetSymbolAddress((void**)&W1h_lo, g_W1h_lo);
    cudaGetSymbolAddress((void**)&W2i_hi, g_W2i_hi);
    cudaGetSymbolAddress((void**)&W2i_lo, g_W2i_lo);
    cudaGetSymbolAddress((void**)&W2h_hi, g_W2h_hi);
    cudaGetSymbolAddress((void**)&W2h_lo, g_W2h_lo);
    cudaGetSymbolAddress((void**)&W3i_hi, g_W3i_hi);
    cudaGetSymbolAddress((void**)&W3i_lo, g_W3i_lo);
    cudaGetSymbolAddress((void**)&W3h_hi, g_W3h_hi);
    cudaGetSymbolAddress((void**)&W3h_lo, g_W3h_lo);
    cudaGetSymbolAddress((void**)&h1_hi, g_h1_hi);
    cudaGetSymbolAddress((void**)&h1_lo, g_h1_lo);
    cudaGetSymbolAddress((void**)&h2_hi, g_h2_hi);
    cudaGetSymbolAddress((void**)&h2_lo, g_h2_lo);
    cudaGetSymbolAddress((void**)&h3_hi, g_h3_hi);
    cudaGetSymbolAddress((void**)&h3_lo, g_h3_lo);
    cudaGetSymbolAddress((void**)&c1, g_c1);
    cudaGetSymbolAddress((void**)&c2, g_c2);
    cudaGetSymbolAddress((void**)&c3, g_c3);
    cudaGetSymbolAddress((void**)&hf1, g_hf1);
    cudaGetSymbolAddress((void**)&hf2, g_hf2);
    cudaGetSymbolAddress((void**)&hf3, g_hf3);

    cudaFuncSetAttribute(lstm_mma_kernel<DIN, H1>,
                         cudaFuncAttributeMaxDynamicSharedMemorySize, DYN_SMEM_BYTES);
    cudaFuncSetAttribute(lstm_mma_kernel<H1, H2>,
                         cudaFuncAttributeMaxDynamicSharedMemorySize, DYN_SMEM_BYTES);
    cudaFuncSetAttribute(lstm_mma_kernel<H2, H3>,
                         cudaFuncAttributeMaxDynamicSharedMemorySize, DYN_SMEM_BYTES);

    split_kernel<<<2048, 256>>>(x, x_hi, x_lo, TT * BB * DIN);
    split_kernel<<<1024, 256>>>(Wih1, W1i_hi, W1i_lo, 4 * H1 * DIN);
    split_kernel<<<1024, 256>>>(Whh1, W1h_hi, W1h_lo, 4 * H1 * H1);
    split_kernel<<<1024, 256>>>(Wih2, W2i_hi, W2i_lo, 4 * H2 * H1);
    split_kernel<<<1024, 256>>>(Whh2, W2h_hi, W2h_lo, 4 * H2 * H2);
    split_kernel<<<1024, 256>>>(Wih3, W3i_hi, W3i_lo, 4 * H3 * H2);
    split_kernel<<<1024, 256>>>(Whh3, W3h_hi, W3h_lo, 4 * H3 * H3);
    init_state_kernel<<<512, 256>>>();

    for (int t = 0; t < TT; ++t) {
        const bf16* xt_hi = x_hi + (size_t)t * BB * DIN;
        const bf16* xt_lo = x_lo + (size_t)t * BB * DIN;

        lstm_mma_kernel<DIN, H1><<<dim3(H1 / 16, 4), 256, DYN_SMEM_BYTES>>>(
            xt_hi, xt_lo, h1_hi, h1_lo,
            W1i_hi, W1i_lo, W1h_hi, W1h_lo, bih1, bhh1,
            c1, hf1, h1_hi, h1_lo);

        lstm_mma_kernel<H1, H2><<<dim3(H2 / 16, 4), 256, DYN_SMEM_BYTES>>>(
            h1_hi, h1_lo, h2_hi, h2_lo,
            W2i_hi, W2i_lo, W2h_hi, W2h_lo, bih2, bhh2,
            c2, hf2, h2_hi, h2_lo);

        lstm_mma_kernel<H2, H3><<<dim3(H3 / 16, 4), 256, DYN_SMEM_BYTES>>>(
            h2_hi, h2_lo, h3_hi, h3_lo,
            W3i_hi, W3i_lo, W3h_hi, W3h_lo, bih3, bhh3,
            c3, hf3, h3_hi, h3_lo);
    }

    finalize_kernel<<<256, 256>>>(out);
}

// round 5
// speedup vs baseline: 3.2800x; 1.2497x over previous
#include <cuda_runtime.h>
#include <cuda_bf16.h>
#include <math.h>
#include <cstdint>

#define TT 128
#define BB 256
#define DIN 512
#define H1 1024
#define H2 1024
#define H3 512

typedef __nv_bfloat16 bf16;

// ---------------- persistent device storage ---------------------------------
__device__ bf16 g_x_hi[TT * BB * DIN];
__device__ bf16 g_x_lo[TT * BB * DIN];
__device__ float g_xpre[(size_t)TT * BB * 4 * H1];   // precomputed x@Wih1^T (512MB)

__device__ bf16 g_W1h_hi[4 * H1 * H1],  g_W1h_lo[4 * H1 * H1];
__device__ bf16 g_W1i_hi[4 * H1 * DIN], g_W1i_lo[4 * H1 * DIN];
__device__ bf16 g_W2i_hi[4 * H2 * H1],  g_W2i_lo[4 * H2 * H1];
__device__ bf16 g_W2h_hi[4 * H2 * H2],  g_W2h_lo[4 * H2 * H2];
__device__ bf16 g_W3i_hi[4 * H3 * H2],  g_W3i_lo[4 * H3 * H2];
__device__ bf16 g_W3h_hi[4 * H3 * H3],  g_W3h_lo[4 * H3 * H3];

__device__ bf16 g_h1_hi[2][BB * H1], g_h1_lo[2][BB * H1];
__device__ bf16 g_h2_hi[2][BB * H2], g_h2_lo[2][BB * H2];
__device__ bf16 g_h3_hi[2][BB * H3], g_h3_lo[2][BB * H3];

__device__ float g_c1[BB * H1], g_c2[BB * H2], g_c3[BB * H3];
__device__ float g_hf1[BB * H1], g_hf2[BB * H2], g_hf3[BB * H3];

// ---------------- helpers ----------------------------------------------------
__device__ __forceinline__ uint32_t smem_u32(const void* p) {
    uint32_t a;
    asm("{ .reg .u64 t; cvta.to.shared.u64 t, %1; cvt.u32.u64 %0, t; }" : "=r"(a) : "l"(p));
    return a;
}
__device__ __forceinline__ void cp16(uint32_t smem, const void* gmem) {
    asm volatile("cp.async.cg.shared.global [%0], [%1], 16;\n" ::"r"(smem), "l"(gmem));
}
#define CP_COMMIT() asm volatile("cp.async.commit_group;\n" ::: "memory")
#define CP_WAIT(n)  asm volatile("cp.async.wait_group %0;\n" ::"n"(n) : "memory")

__device__ __forceinline__ void ldsm4(unsigned* d, uint32_t addr) {
    asm volatile("ldmatrix.sync.aligned.m8n8.x4.shared.b16 {%0,%1,%2,%3}, [%4];"
                 : "=r"(d[0]), "=r"(d[1]), "=r"(d[2]), "=r"(d[3]) : "r"(addr));
}
__device__ __forceinline__ void mma_bf16(float* c, const unsigned* a, unsigned b0, unsigned b1) {
    asm volatile(
        "mma.sync.aligned.m16n8k16.row.col.f32.bf16.bf16.f32 "
        "{%0,%1,%2,%3},{%4,%5,%6,%7},{%8,%9},{%0,%1,%2,%3};\n"
        : "+f"(c[0]), "+f"(c[1]), "+f"(c[2]), "+f"(c[3])
        : "r"(a[0]), "r"(a[1]), "r"(a[2]), "r"(a[3]), "r"(b0), "r"(b1));
}
__device__ __forceinline__ float sigm(float x) { return 1.0f / (1.0f + __expf(-x)); }

// ---------------------------------------------------------------------------
// Tiled 3-term bf16-split GEMM over Keff = 3*(K1+K2), tile 128(batch) x 64
// (16 j x 4 gates). 8 warps = 2(m) x 4(gate). 4-stage cp.async pipeline.
// PRE=true: store raw fp32 gates to gout (x@Wih precompute).
// PRE=false: fused LSTM epilogue (c/h update, bf16 hi/lo re-split), optional
//            xpre added to gates.
// ---------------------------------------------------------------------------
#define BM 128
#define BN 64
#define PITCH 72
#define A_STG (BM * PITCH)
#define B_STG (BN * PITCH)
#define STG_ELEMS (A_STG + B_STG)
#define DYN_BYTES (4 * STG_ELEMS * 2)   // 110592 bytes

template <int K1, int K2, int HH, bool PRE>
__global__ __launch_bounds__(256, 2)
void gemm_kernel(const bf16* __restrict__ Ai_hi, const bf16* __restrict__ Ai_lo,
                 const bf16* __restrict__ Ah_hi, const bf16* __restrict__ Ah_lo,
                 const bf16* __restrict__ Wi_hi, const bf16* __restrict__ Wi_lo,
                 const bf16* __restrict__ Wh_hi, const bf16* __restrict__ Wh_lo,
                 const float* __restrict__ bih, const float* __restrict__ bhh,
                 const float* __restrict__ xpre,
                 float* __restrict__ c, float* __restrict__ hf,
                 bf16* __restrict__ ho_hi, bf16* __restrict__ ho_lo,
                 float* __restrict__ gout)
{
    constexpr int KK = K1 + K2;
    constexpr int NCH = 3 * KK / 64;

    extern __shared__ __align__(16) bf16 dyn[];
    const uint32_t sbase = smem_u32(dyn);

    const int tid = threadIdx.x;
    const int wid = tid >> 5, lane = tid & 31;
    const int wm = wid >> 2, wn = wid & 3;     // m-half (64 rows), gate
    const int j0 = blockIdx.x * 16;
    const int b0 = blockIdx.y * BM;

    float acc[4][2][4];
#pragma unroll
    for (int mi = 0; mi < 4; ++mi)
#pragma unroll
        for (int nj = 0; nj < 2; ++nj)
#pragma unroll
            for (int r = 0; r < 4; ++r) acc[mi][nj][r] = 0.0f;

    auto load_stage = [&](int ci, int s) {
        const int kg = ci * 64;
        const int term = kg / KK;
        const int kk = kg - term * KK;
        const bf16 *A, *W;
        int col, ld;
        if (kk < K1) {
            A = (term == 1) ? Ai_lo : Ai_hi;
            W = (term == 2) ? Wi_lo : Wi_hi;
            col = kk; ld = K1;
        } else {
            A = (term == 1) ? Ah_lo : Ah_hi;
            W = (term == 2) ? Wh_lo : Wh_hi;
            col = kk - K1; ld = K2;
        }
        const uint32_t abase = sbase + (uint32_t)(s * STG_ELEMS) * 2;
        const uint32_t bbase = abase + A_STG * 2;
#pragma unroll
        for (int it = 0; it < 4; ++it) {           // A: 128 rows x 8 quads
            const int idx = tid + it * 256;
            const int r = idx >> 3, q = idx & 7;
            cp16(abase + (uint32_t)(r * PITCH + q * 8) * 2,
                 A + (size_t)(b0 + r) * ld + col + q * 8);
        }
#pragma unroll
        for (int it = 0; it < 2; ++it) {           // B: 64 rows x 8 quads
            const int idx = tid + it * 256;
            const int r = idx >> 3, q = idx & 7;
            const int gate = r >> 4, jl = r & 15;
            cp16(bbase + (uint32_t)(r * PITCH + q * 8) * 2,
                 W + (size_t)(gate * HH + j0 + jl) * ld + col + q * 8);
        }
        CP_COMMIT();
    };

    auto compute = [&](int s) {
        const uint32_t abase = sbase + (uint32_t)(s * STG_ELEMS) * 2;
        const uint32_t bbase = abase + A_STG * 2;
        const int arow_off = lane & 15, acol_off = (lane >> 4) << 3;
        const int brow_off = (((lane >> 3) & 1) << 3) + (lane & 7);
        const int bcol_off = (lane >> 4) << 3;
#pragma unroll
        for (int kh = 0; kh < 4; ++kh) {
            const int kc = kh * 16;
            unsigned a[4][4], b[4];
            {
                const int row = wn * 16 + brow_off;
                ldsm4(b, bbase + (uint32_t)(row * PITCH + kc + bcol_off) * 2);
            }
#pragma unroll
            for (int mi = 0; mi < 4; ++mi) {
                const int row = wm * 64 + mi * 16 + arow_off;
                ldsm4(a[mi], abase + (uint32_t)(row * PITCH + kc + acol_off) * 2);
            }
#pragma unroll
            for (int mi = 0; mi < 4; ++mi)
#pragma unroll
                for (int nj = 0; nj < 2; ++nj)
                    mma_bf16(acc[mi][nj], a[mi], b[nj], b[nj + 2]);
        }
    };

    load_stage(0, 0);
    load_stage(1, 1);
    load_stage(2, 2);

    for (int ci = 0; ci < NCH; ++ci) {
        const int rem = NCH - 1 - ci;
        if (rem >= 2)      { CP_WAIT(2); }
        else if (rem == 1) { CP_WAIT(1); }
        else               { CP_WAIT(0); }
        __syncthreads();
        if (ci + 3 < NCH) load_stage(ci + 3, (ci + 3) & 3);
        compute(ci & 3);
    }
    __syncthreads();     // stage smem is about to be reused for gate staging

    // stage gates to smem (aliased over pipeline stages): gsm[4][128][17]
    float* gsm = reinterpret_cast<float*>(dyn);
    const int lg = lane >> 2, tg = lane & 3;
#pragma unroll
    for (int mi = 0; mi < 4; ++mi)
#pragma unroll
        for (int nj = 0; nj < 2; ++nj) {
            const int r0 = wm * 64 + mi * 16 + lg;
            const int jc = nj * 8 + tg * 2;
            float* base = gsm + wn * (BM * 17);
            base[r0 * 17 + jc]           = acc[mi][nj][0];
            base[r0 * 17 + jc + 1]       = acc[mi][nj][1];
            base[(r0 + 8) * 17 + jc]     = acc[mi][nj][2];
            base[(r0 + 8) * 17 + jc + 1] = acc[mi][nj][3];
        }
    __syncthreads();

#pragma unroll
    for (int it = 0; it < 8; ++it) {
        const int e = tid + it * 256;      // 2048 = 128*16
        const int bl = e >> 4, jl = e & 15;
        const int b = b0 + bl;
        const int j = j0 + jl;
        if (PRE) {
            float* orow = gout + (size_t)b * (4 * HH) + j;
#pragma unroll
            for (int g = 0; g < 4; ++g)
                orow[g * HH] = gsm[g * (BM * 17) + bl * 17 + jl];
        } else {
            float gv[4];
#pragma unroll
            for (int g = 0; g < 4; ++g)
                gv[g] = gsm[g * (BM * 17) + bl * 17 + jl] + bih[g * HH + j] + bhh[g * HH + j];
            if (xpre) {
                const float* xr = xpre + (size_t)b * (4 * HH) + j;
#pragma unroll
                for (int g = 0; g < 4; ++g) gv[g] += xr[g * HH];
            }
            const float i_ = sigm(gv[0]);
            const float f_ = sigm(gv[1]);
            const float g_ = tanhf(gv[2]);
            const float o_ = sigm(gv[3]);
            const size_t off = (size_t)b * HH + j;
            const float cn = f_ * c[off] + i_ * g_;
            c[off] = cn;
            const float hn = o_ * tanhf(cn);
            hf[off] = hn;
            const bf16 hh = __float2bfloat16(hn);
            ho_hi[off] = hh;
            ho_lo[off] = __float2bfloat16(hn - __bfloat162float(hh));
        }
    }
}

// ---------------- prep / init / finalize ------------------------------------
__global__ void split_kernel(const float* __restrict__ src, bf16* __restrict__ hi,
                             bf16* __restrict__ lo, int n) {
    int i = blockIdx.x * blockDim.x + threadIdx.x;
    const int st = gridDim.x * blockDim.x;
    for (; i < n; i += st) {
        const float v = src[i];
        const bf16 h = __float2bfloat16(v);
        hi[i] = h;
        lo[i] = __float2bfloat16(v - __bfloat162float(h));
    }
}

__global__ void init_state_kernel() {
    int idx = blockIdx.x * blockDim.x + threadIdx.x;
    const int st = gridDim.x * blockDim.x;
    const int N1 = BB * H1, N3 = BB * H3;
    const bf16 z = __float2bfloat16(0.0f);
    for (int i = idx; i < N1; i += st) {
        g_h1_hi[0][i] = z; g_h1_lo[0][i] = z; g_h1_hi[1][i] = z; g_h1_lo[1][i] = z;
        g_h2_hi[0][i] = z; g_h2_lo[0][i] = z; g_h2_hi[1][i] = z; g_h2_lo[1][i] = z;
        g_c1[i] = 0.f; g_c2[i] = 0.f;
    }
    for (int i = idx; i < N3; i += st) {
        g_h3_hi[0][i] = z; g_h3_lo[0][i] = z; g_h3_hi[1][i] = z; g_h3_lo[1][i] = z;
        g_c3[i] = 0.f;
    }
}

__global__ void finalize_kernel(float* __restrict__ out) {
    int idx = blockIdx.x * blockDim.x + threadIdx.x;
    const int st = gridDim.x * blockDim.x;
    const int N1 = BB * H1, N3 = BB * H3;
    for (int i = idx; i < N1; i += st) {
        out[0 * N1 + i] = g_hf1[i];
        out[1 * N1 + i] = g_c1[i];
        out[2 * N1 + i] = g_hf2[i];
        out[3 * N1 + i] = g_c2[i];
    }
    for (int i = idx; i < N3; i += st) {
        out[4 * N1 + i] = g_hf3[i];
        out[4 * N1 + N3 + i] = g_c3[i];
    }
}

// ---------------- launch ----------------------------------------------------
extern "C" void kernel_launch(void* const* d_in, const int* in_sizes, int n_in,
                              void* d_out, int out_size) {
    const float* x    = (const float*)d_in[0];
    const float* Wih1 = (const float*)d_in[1];
    const float* Whh1 = (const float*)d_in[2];
    const float* bih1 = (const float*)d_in[3];
    const float* bhh1 = (const float*)d_in[4];
    const float* Wih2 = (const float*)d_in[5];
    const float* Whh2 = (const float*)d_in[6];
    const float* bih2 = (const float*)d_in[7];
    const float* bhh2 = (const float*)d_in[8];
    const float* Wih3 = (const float*)d_in[9];
    const float* Whh3 = (const float*)d_in[10];
    const float* bih3 = (const float*)d_in[11];
    const float* bhh3 = (const float*)d_in[12];
    float* out = (float*)d_out;

    bf16 *x_hi, *x_lo;
    bf16 *W1i_hi, *W1i_lo, *W1h_hi, *W1h_lo;
    bf16 *W2i_hi, *W2i_lo, *W2h_hi, *W2h_lo;
    bf16 *W3i_hi, *W3i_lo, *W3h_hi, *W3h_lo;
    bf16 *h1_hi, *h1_lo, *h2_hi, *h2_lo, *h3_hi, *h3_lo;
    float *c1, *c2, *c3, *hf1, *hf2, *hf3, *xpre;

    cudaGetSymbolAddress((void**)&x_hi, g_x_hi);
    cudaGetSymbolAddress((void**)&x_lo, g_x_lo);
    cudaGetSymbolAddress((void**)&xpre, g_xpre);
    cudaGetSymbolAddress((void**)&W1i_hi, g_W1i_hi);
    cudaGetSymbolAddress((void**)&W1i_lo, g_W1i_lo);
    cudaGetSymbolAddress((void**)&W1h_hi, g_W1h_hi);
    cudaGetSymbolAddress((void**)&W1h_lo, g_W1h_lo);
    cudaGetSymbolAddress((void**)&W2i_hi, g_W2i_hi);
    cudaGetSymbolAddress((void**)&W2i_lo, g_W2i_lo);
    cudaGetSymbolAddress((void**)&W2h_hi, g_W2h_hi);
    cudaGetSymbolAddress((void**)&W2h_lo, g_W2h_lo);
    cudaGetSymbolAddress((void**)&W3i_hi, g_W3i_hi);
    cudaGetSymbolAddress((void**)&W3i_lo, g_W3i_lo);
    cudaGetSymbolAddress((void**)&W3h_hi, g_W3h_hi);
    cudaGetSymbolAddress((void**)&W3h_lo, g_W3h_lo);
    cudaGetSymbolAddress((void**)&h1_hi, g_h1_hi);
    cudaGetSymbolAddress((void**)&h1_lo, g_h1_lo);
    cudaGetSymbolAddress((void**)&h2_hi, g_h2_hi);
    cudaGetSymbolAddress((void**)&h2_lo, g_h2_lo);
    cudaGetSymbolAddress((void**)&h3_hi, g_h3_hi);
    cudaGetSymbolAddress((void**)&h3_lo, g_h3_lo);
    cudaGetSymbolAddress((void**)&c1, g_c1);
    cudaGetSymbolAddress((void**)&c2, g_c2);
    cudaGetSymbolAddress((void**)&c3, g_c3);
    cudaGetSymbolAddress((void**)&hf1, g_hf1);
    cudaGetSymbolAddress((void**)&hf2, g_hf2);
    cudaGetSymbolAddress((void**)&hf3, g_hf3);

    cudaFuncSetAttribute(gemm_kernel<DIN, 0, H1, true>,
                         cudaFuncAttributeMaxDynamicSharedMemorySize, DYN_BYTES);
    cudaFuncSetAttribute(gemm_kernel<H1, 0, H1, false>,
                         cudaFuncAttributeMaxDynamicSharedMemorySize, DYN_BYTES);
    cudaFuncSetAttribute(gemm_kernel<H1, H2, H2, false>,
                         cudaFuncAttributeMaxDynamicSharedMemorySize, DYN_BYTES);
    cudaFuncSetAttribute(gemm_kernel<H2, H3, H3, false>,
                         cudaFuncAttributeMaxDynamicSharedMemorySize, DYN_BYTES);

    // streams/events created once, reused on every call (work is identical
    // per call; these are host resources, not device memory)
    static cudaStream_t s1 = nullptr, s2 = nullptr, s3 = nullptr;
    static cudaEvent_t ev1r[4], ev2r[4], ev3r[4], evFork, evJ1, evJ2, evJ3;
    if (!s1) {
        cudaStreamCreateWithFlags(&s1, cudaStreamNonBlocking);
        cudaStreamCreateWithFlags(&s2, cudaStreamNonBlocking);
        cudaStreamCreateWithFlags(&s3, cudaStreamNonBlocking);
        for (int i = 0; i < 4; ++i) {
            cudaEventCreateWithFlags(&ev1r[i], cudaEventDisableTiming);
            cudaEventCreateWithFlags(&ev2r[i], cudaEventDisableTiming);
            cudaEventCreateWithFlags(&ev3r[i], cudaEventDisableTiming);
        }
        cudaEventCreateWithFlags(&evFork, cudaEventDisableTiming);
        cudaEventCreateWithFlags(&evJ1, cudaEventDisableTiming);
        cudaEventCreateWithFlags(&evJ2, cudaEventDisableTiming);
        cudaEventCreateWithFlags(&evJ3, cudaEventDisableTiming);
    }

    // -------- prologue (legacy stream) --------
    split_kernel<<<2048, 256>>>(x, x_hi, x_lo, TT * BB * DIN);
    split_kernel<<<1024, 256>>>(Wih1, W1i_hi, W1i_lo, 4 * H1 * DIN);
    split_kernel<<<1024, 256>>>(Whh1, W1h_hi, W1h_lo, 4 * H1 * H1);
    split_kernel<<<1024, 256>>>(Wih2, W2i_hi, W2i_lo, 4 * H2 * H1);
    split_kernel<<<1024, 256>>>(Whh2, W2h_hi, W2h_lo, 4 * H2 * H2);
    split_kernel<<<1024, 256>>>(Wih3, W3i_hi, W3i_lo, 4 * H3 * H2);
    split_kernel<<<1024, 256>>>(Whh3, W3h_hi, W3h_lo, 4 * H3 * H3);
    init_state_kernel<<<512, 256>>>();

    // big precompute: X1 = x @ Wih1^T for all T*B rows
    gemm_kernel<DIN, 0, H1, true><<<dim3(H1 / 16, TT * BB / BM), 256, DYN_BYTES>>>(
        x_hi, x_lo, nullptr, nullptr, W1i_hi, W1i_lo, nullptr, nullptr,
        nullptr, nullptr, nullptr, nullptr, nullptr, nullptr, nullptr, xpre);

    cudaEventRecord(evFork, 0);
    cudaStreamWaitEvent(s1, evFork, 0);
    cudaStreamWaitEvent(s2, evFork, 0);
    cudaStreamWaitEvent(s3, evFork, 0);

    const int N1 = BB * H1, N2 = BB * H2, N3 = BB * H3;

    for (int t = 0; t < TT; ++t) {
        const int pi = t & 1, po = (t + 1) & 1;

        // L1 (recurrent-only) on s1; WAR on h1[po] vs L2(t-2) read
        if (t >= 2) cudaStreamWaitEvent(s1, ev2r[(t - 2) & 3], 0);
        gemm_kernel<H1, 0, H1, false><<<dim3(H1 / 16, BB / BM), 256, DYN_BYTES, s1>>>(
            h1_hi + pi * N1, h1_lo + pi * N1, nullptr, nullptr,
            W1h_hi, W1h_lo, nullptr, nullptr,
            bih1, bhh1, xpre + (size_t)t * BB * 4 * H1,
            c1, hf1, h1_hi + po * N1, h1_lo + po * N1, nullptr);
        cudaEventRecord(ev1r[t & 3], s1);

        // L2 on s2: needs h1(t); WAR on h2[po] vs L3(t-2) read
        cudaStreamWaitEvent(s2, ev1r[t & 3], 0);
        if (t >= 2) cudaStreamWaitEvent(s2, ev3r[(t - 2) & 3], 0);
        gemm_kernel<H1, H2, H2, false><<<dim3(H2 / 16, BB / BM), 256, DYN_BYTES, s2>>>(
            h1_hi + po * N1, h1_lo + po * N1, h2_hi + pi * N2, h2_lo + pi * N2,
            W2i_hi, W2i_lo, W2h_hi, W2h_lo,
            bih2, bhh2, nullptr,
            c2, hf2, h2_hi + po * N2, h2_lo + po * N2, nullptr);
        cudaEventRecord(ev2r[t & 3], s2);

        // L3 on s3: needs h2(t)
        cudaStreamWaitEvent(s3, ev2r[t & 3], 0);
        gemm_kernel<H2, H3, H3, false><<<dim3(H3 / 16, BB / BM), 256, DYN_BYTES, s3>>>(
            h2_hi + po * N2, h2_lo + po * N2, h3_hi + pi * N3, h3_lo + pi * N3,
            W3i_hi, W3i_lo, W3h_hi, W3h_lo,
            bih3, bhh3, nullptr,
            c3, hf3, h3_hi + po * N3, h3_lo + po * N3, nullptr);
        cudaEventRecord(ev3r[t & 3], s3);
    }

    // join back to legacy stream
    cudaEventRecord(evJ1, s1);
    cudaEventRecord(evJ2, s2);
    cudaEventRecord(evJ3, s3);
    cudaStreamWaitEvent(0, evJ1, 0);
    cudaStreamWaitEvent(0, evJ2, 0);
    cudaStreamWaitEvent(0, evJ3, 0);

    finalize_kernel<<<256, 256>>>(out);
}